// round 7
// baseline (speedup 1.0000x reference)
#include <cuda_runtime.h>
#include <cuda_bf16.h>
#include <cstdint>

#define Nn 100000
#define Ee 600000

// ---------------- scratch (allocation-free: __device__ globals) --------------
__device__ float g_agg[Nn * 128];
__device__ float g_h[Nn * 128];
__device__ __nv_bfloat16 g_wb[6][2][128 * 136];
__device__ __nv_bfloat16 g_web[2][2][128 * 40];
// edge sort scratch
__device__ int g_cnt[Nn];
__device__ int g_scan[Nn];
__device__ int g_bsum[512];
__device__ int g_cur[Nn];
__device__ int g_perm[Ee];
__device__ int g_src2[Ee];
__device__ int g_dst2[Ee];

// ---------------- helpers -----------------------------------------------------
__device__ __forceinline__ void red_add_v4(float* p, float4 v) {
    asm volatile("red.global.add.v4.f32 [%0], {%1, %2, %3, %4};"
                 :: "l"(p), "f"(v.x), "f"(v.y), "f"(v.z), "f"(v.w)
                 : "memory");
}
__device__ __forceinline__ uint32_t smem_u32(const void* p) {
    return (uint32_t)__cvta_generic_to_shared(p);
}
__device__ __forceinline__ void cp_async16(uint32_t dst, const void* src) {
    asm volatile("cp.async.cg.shared.global [%0], [%1], 16;"
                 :: "r"(dst), "l"(src));
}
__device__ __forceinline__ void cp_commit() {
    asm volatile("cp.async.commit_group;");
}
__device__ __forceinline__ void cp_wait0() {
    asm volatile("cp.async.wait_group 0;" ::: "memory");
}
__device__ __forceinline__ void ldx4(uint32_t* r, uint32_t addr) {
    asm volatile("ldmatrix.sync.aligned.m8n8.x4.shared.b16 {%0, %1, %2, %3}, [%4];"
                 : "=r"(r[0]), "=r"(r[1]), "=r"(r[2]), "=r"(r[3]) : "r"(addr));
}
__device__ __forceinline__ void mma_bf16(float* c, const uint32_t* a,
                                         const uint32_t* b) {
    asm volatile("mma.sync.aligned.m16n8k16.row.col.f32.bf16.bf16.f32 "
                 "{%0, %1, %2, %3}, {%4, %5, %6, %7}, {%8, %9}, {%0, %1, %2, %3};"
                 : "+f"(c[0]), "+f"(c[1]), "+f"(c[2]), "+f"(c[3])
                 : "r"(a[0]), "r"(a[1]), "r"(a[2]), "r"(a[3]),
                   "r"(b[0]), "r"(b[1]));
}
__device__ __forceinline__ uint32_t bf2_u32(__nv_bfloat162 x) {
    uint32_t r;
    memcpy(&r, &x, 4);
    return r;
}
__device__ __forceinline__ uint32_t split_hi2(float a, float b, uint32_t& lo) {
    __nv_bfloat162 h = __floats2bfloat162_rn(a, b);
    __nv_bfloat162 l = __floats2bfloat162_rn(a - __bfloat162float(h.x),
                                             b - __bfloat162float(h.y));
    lo = bf2_u32(l);
    return bf2_u32(h);
}

// ---------------- init copy ---------------------------------------------------
__global__ void __launch_bounds__(256) copy_kernel(float4* __restrict__ dst,
                                                   const float4* __restrict__ src,
                                                   int n4) {
    int i = blockIdx.x * blockDim.x + threadIdx.x;
    if (i < n4) dst[i] = src[i];
}

// ---------------- counting sort of edges by dst --------------------------------
__global__ void __launch_bounds__(256) k_zero(int* cnt) {
    int i = blockIdx.x * 256 + threadIdx.x;
    if (i < Nn) cnt[i] = 0;
}
__global__ void __launch_bounds__(256) k_hist(const int* __restrict__ dst, int* cnt) {
    int e = blockIdx.x * 256 + threadIdx.x;
    if (e < Ee) atomicAdd(&cnt[dst[e]], 1);
}
__global__ void __launch_bounds__(256) k_scan1(const int* __restrict__ cnt,
                                               int* scan, int* bsum) {
    __shared__ int s[256];
    int i = blockIdx.x * 256 + threadIdx.x;
    int v = (i < Nn) ? cnt[i] : 0;
    s[threadIdx.x] = v;
    __syncthreads();
#pragma unroll
    for (int o = 1; o < 256; o <<= 1) {
        int t = (threadIdx.x >= o) ? s[threadIdx.x - o] : 0;
        __syncthreads();
        s[threadIdx.x] += t;
        __syncthreads();
    }
    if (i < Nn) scan[i] = s[threadIdx.x] - v;   // local exclusive
    if (threadIdx.x == 255) bsum[blockIdx.x] = s[255];
}
__global__ void __launch_bounds__(512) k_scan2(int* bsum, int nblk) {
    __shared__ int s[512];
    int t = threadIdx.x;
    int v = (t < nblk) ? bsum[t] : 0;
    s[t] = v;
    __syncthreads();
#pragma unroll
    for (int o = 1; o < 512; o <<= 1) {
        int x = (t >= o) ? s[t - o] : 0;
        __syncthreads();
        s[t] += x;
        __syncthreads();
    }
    if (t < nblk) bsum[t] = s[t] - v;           // exclusive
}
__global__ void __launch_bounds__(256) k_scan3(const int* __restrict__ scan,
                                               const int* __restrict__ bsum, int* cur) {
    int i = blockIdx.x * 256 + threadIdx.x;
    if (i < Nn) cur[i] = scan[i] + bsum[blockIdx.x];
}
__global__ void __launch_bounds__(256)
k_scatter(const int* __restrict__ src, const int* __restrict__ dst, int* cur,
          int* perm, int* src2, int* dst2) {
    int e = blockIdx.x * 256 + threadIdx.x;
    if (e < Ee) {
        int d = dst[e];
        int p = atomicAdd(&cur[d], 1);
        perm[p] = e;
        src2[p] = src[e];
        dst2[p] = d;
    }
}

// ---------------- fused weight prep (one launch) -------------------------------
__global__ void __launch_bounds__(256)
prep_all(const float* __restrict__ W1a, const float* __restrict__ W1b,
         const float* __restrict__ W2a, const float* __restrict__ W2b,
         const float* __restrict__ Wfc1, const float* __restrict__ Wfc2,
         const float* __restrict__ We1, const float* __restrict__ We2,
         __nv_bfloat16* __restrict__ wb, __nv_bfloat16* __restrict__ web) {
    int id = blockIdx.x * 256 + threadIdx.x;
    if (id < 81920) {
        int m = id / 16384, e = id % 16384;
        const float* W = (m == 0) ? W1a : (m == 1) ? W1b
                       : (m == 2) ? W2a : (m == 3) ? W2b : Wfc1;
        int n = e >> 7, k = e & 127;
        float v = W[k * 128 + n];
        __nv_bfloat16 h = __float2bfloat16_rn(v);
        __nv_bfloat16 l = __float2bfloat16_rn(v - __bfloat162float(h));
        wb[(size_t)m * 2 * 128 * 136 + n * 136 + k] = h;
        wb[((size_t)m * 2 + 1) * 128 * 136 + n * 136 + k] = l;
    } else if (id < 90112) {
        int e = id - 81920;
        int n = e >> 7, k = e & 127;
        float v = Wfc2[k * 64 + n];
        __nv_bfloat16 h = __float2bfloat16_rn(v);
        __nv_bfloat16 l = __float2bfloat16_rn(v - __bfloat162float(h));
        wb[(size_t)5 * 2 * 128 * 136 + n * 136 + k] = h;
        wb[((size_t)5 * 2 + 1) * 128 * 136 + n * 136 + k] = l;
    } else if (id < 98304) {
        int e = id - 90112;
        int m = e >> 12; e &= 4095;
        int n = e >> 5, k = e & 31;
        const float* We = m ? We2 : We1;
        float v = We[k * 128 + n];
        __nv_bfloat16 h = __float2bfloat16_rn(v);
        __nv_bfloat16 l = __float2bfloat16_rn(v - __bfloat162float(h));
        web[(size_t)m * 2 * 128 * 40 + n * 40 + k] = h;
        web[((size_t)m * 2 + 1) * 128 * 40 + n * 40 + k] = l;
    }
}

// ---------------- HMMA fused edge kernel (sorted, run-aggregating) -------------
// Dynamic smem layout (68608 B):
//   [0, 67584): union of { We/ef MMA tiles } then { msg tile 128x132 fp32 }
//   [67584): ssrc[128], sdst[128]
__global__ void __launch_bounds__(256, 2)
edge_kernel(const float* __restrict__ xin,
            const int* __restrict__ src2, const int* __restrict__ dst2,
            const int* __restrict__ perm,
            const float* __restrict__ ef,
            const __nv_bfloat16* __restrict__ Weh,
            const __nv_bfloat16* __restrict__ Wel,
            const float* __restrict__ be,
            float* __restrict__ agg) {
    extern __shared__ char sm[];
    const uint32_t s0   = smem_u32(sm);
    const uint32_t sWeh = s0, sWel = s0 + 10240;
    const uint32_t sEfh = s0 + 20480, sEfl = s0 + 30720;
    const uint32_t smsg = s0;                       // union, pitch 132 floats
    float* msgf = (float*)sm;
    int* ssrc = (int*)(sm + 67584);
    int* sdst = (int*)(sm + 68096);

    const int tid  = threadIdx.x;
    const int wid  = tid >> 5;
    const int lane = tid & 31;
    const int base = blockIdx.x * 128;
    const int nvalid = min(128, Ee - base);

    for (int i = tid; i < 640; i += 256) {
        cp_async16(sWeh + i * 16, (const char*)Weh + i * 16);
        cp_async16(sWel + i * 16, (const char*)Wel + i * 16);
    }
    cp_commit();

    if (tid < 128) {
        int e = min(base + tid, Ee - 1);
        ssrc[tid] = src2[e];
        sdst[tid] = dst2[e];
    }

    // ef tile via perm: 128 edges x 32 k, fp32 -> bf16 hi/lo, pitch 40
    {
        const int edge = tid >> 1, half = tid & 1;
        int ge = perm[min(base + edge, Ee - 1)];
        const float4* ap = (const float4*)(ef + (size_t)ge * 32 + half * 16);
        const uint32_t dh = sEfh + edge * 80 + half * 32;
        const uint32_t dl = sEfl + edge * 80 + half * 32;
#pragma unroll
        for (int i = 0; i < 4; i++) {
            float4 v = ap[i];
            uint32_t l0, l1;
            uint32_t h0 = split_hi2(v.x, v.y, l0);
            uint32_t h1 = split_hi2(v.z, v.w, l1);
            asm volatile("st.shared.v2.b32 [%0], {%1, %2};"
                         :: "r"(dh + i * 8), "r"(h0), "r"(h1));
            asm volatile("st.shared.v2.b32 [%0], {%1, %2};"
                         :: "r"(dl + i * 8), "r"(l0), "r"(l1));
        }
    }
    cp_wait0();
    __syncthreads();

    const int g = lane >> 2, tq = lane & 3;
    const uint32_t aoff = sEfh
        + (uint32_t)(wid * 16 + (lane & 15)) * 80 + ((lane >> 4) ? 16 : 0);
    const uint32_t aloff = aoff + (sEfl - sEfh);
    const int brow = (lane & 7) + ((lane >> 4) << 3);
    const uint32_t boff = sWeh + (uint32_t)brow * 80 + ((lane & 8) ? 16 : 0);
    const uint32_t bloff = boff + (sWel - sWeh);

    // seed with bias (once per edge message)
    float acc[16][4];
#pragma unroll
    for (int ni = 0; ni < 16; ni++) {
        float2 b = __ldg((const float2*)(be + ni * 8 + tq * 2));
        acc[ni][0] = b.x; acc[ni][1] = b.y;
        acc[ni][2] = b.x; acc[ni][3] = b.y;
    }

#pragma unroll
    for (int ks = 0; ks < 2; ks++) {
        uint32_t ah[4], al[4];
        ldx4(ah, aoff + ks * 32);
        ldx4(al, aloff + ks * 32);
#pragma unroll
        for (int np = 0; np < 8; np++) {
            uint32_t rh[4], rl[4];
            ldx4(rh, boff + np * (16 * 80) + ks * 32);
            ldx4(rl, bloff + np * (16 * 80) + ks * 32);
            uint32_t bh0[2] = {rh[0], rh[1]}, bh1[2] = {rh[2], rh[3]};
            uint32_t bl0[2] = {rl[0], rl[1]}, bl1[2] = {rl[2], rl[3]};
            mma_bf16(acc[np * 2],     ah, bh0);
            mma_bf16(acc[np * 2],     ah, bl0);
            mma_bf16(acc[np * 2],     al, bh0);
            mma_bf16(acc[np * 2 + 1], ah, bh1);
            mma_bf16(acc[np * 2 + 1], ah, bl1);
            mma_bf16(acc[np * 2 + 1], al, bh1);
        }
    }
    __syncthreads();          // all ldmatrix reads done -> reuse smem for msg

    // store msg tile (pre-relu, bias included) to smem, pitch 132 floats
    {
        const int er = wid * 16 + g;
#pragma unroll
        for (int ni = 0; ni < 16; ni++) {
            const int col = ni * 8 + tq * 2;
            const uint32_t d0 = smsg + ((uint32_t)er * 132 + col) * 4;
            asm volatile("st.shared.v2.b32 [%0], {%1, %2};"
                         :: "r"(d0), "f"(acc[ni][0]), "f"(acc[ni][1]));
            asm volatile("st.shared.v2.b32 [%0], {%1, %2};"
                         :: "r"(d0 + 8 * 132 * 4), "f"(acc[ni][2]), "f"(acc[ni][3]));
        }
    }
    __syncthreads();

    // run-aggregating epilogue: thread = (col group c: 4 cols) x (16 sorted edges)
    {
        const int c = tid & 31;
        const int e0 = (tid >> 5) * 16;
        float4 racc = make_float4(0.f, 0.f, 0.f, 0.f);
        int cur = -1;
#pragma unroll 1
        for (int i = 0; i < 16; i++) {
            const int e = e0 + i;
            if (e >= nvalid) break;
            const int d = sdst[e];
            float4 ev = *(const float4*)(msgf + e * 132 + c * 4);
            float4 xv = *(const float4*)(xin + (size_t)ssrc[e] * 128 + c * 4);
            float4 m;
            m.x = fmaxf(xv.x + ev.x, 0.f);
            m.y = fmaxf(xv.y + ev.y, 0.f);
            m.z = fmaxf(xv.z + ev.z, 0.f);
            m.w = fmaxf(xv.w + ev.w, 0.f);
            if (d == cur) {
                racc.x += m.x; racc.y += m.y; racc.z += m.z; racc.w += m.w;
            } else {
                if (cur >= 0) red_add_v4(agg + (size_t)cur * 128 + c * 4, racc);
                racc = m;
                cur = d;
            }
        }
        if (cur >= 0) red_add_v4(agg + (size_t)cur * 128 + c * 4, racc);
    }
}

// ---------------- fused two-stage node GEMM (unchanged) ------------------------
template <int COUT2, int ACT1, int ACT2>
__global__ void __launch_bounds__(256, 1)
fgemm(const float* __restrict__ A,
      const __nv_bfloat16* __restrict__ W1h, const __nv_bfloat16* __restrict__ W1l,
      const __nv_bfloat16* __restrict__ W2h, const __nv_bfloat16* __restrict__ W2l,
      const float* __restrict__ b1, const float* __restrict__ b2,
      float* __restrict__ out, float* __restrict__ out2, int nrows, int ntiles) {
    constexpr int NW2 = COUT2 / 4;
    constexpr int NF2 = NW2 / 8;
    constexpr uint32_t AB  = 128 * 136 * 2;
    constexpr uint32_t W1B = 128 * 136 * 2;
    constexpr uint32_t W2B = (uint32_t)COUT2 * 136 * 2;

    extern __shared__ char sm[];
    const uint32_t s0   = smem_u32(sm);
    const uint32_t sAh  = s0,            sAl  = s0 + AB;
    const uint32_t sW1h = s0 + 2 * AB,   sW1l = sW1h + W1B;
    const uint32_t sW2h = sW1l + W1B,    sW2l = sW2h + W2B;

    const int tid  = threadIdx.x;
    const int wid  = tid >> 5;
    const int lane = tid & 31;
    const int mw   = wid >> 2, cw = wid & 3;

    for (int i = tid; i < (int)(W1B / 16); i += 256) {
        cp_async16(sW1h + i * 16, (const char*)W1h + i * 16);
        cp_async16(sW1l + i * 16, (const char*)W1l + i * 16);
    }
    for (int i = tid; i < (int)(W2B / 16); i += 256) {
        cp_async16(sW2h + i * 16, (const char*)W2h + i * 16);
        cp_async16(sW2l + i * 16, (const char*)W2l + i * 16);
    }
    cp_commit();

    const int g = lane >> 2, tq = lane & 3;
    const uint32_t aoff = (uint32_t)(mw * 64 + (lane & 15)) * 272
                        + ((lane >> 4) ? 16 : 0);
    const int brow = (lane & 7) + ((lane >> 4) << 3);
    const uint32_t b1off = (uint32_t)(cw * 32 + brow) * 272 + ((lane & 8) ? 16 : 0);
    const uint32_t b2off = (uint32_t)(cw * NW2 + brow) * 272 + ((lane & 8) ? 16 : 0);

    bool first = true;
    for (int mt = blockIdx.x; mt < ntiles; mt += gridDim.x) {
        const int mbase = mt * 128;
        {
            const int row = tid >> 1, half = tid & 1;
            int grow = min(mbase + row, nrows - 1);
            const float* ap = A + (size_t)grow * 128 + half * 64;
            const uint32_t d = row * 272 + half * 128;
#pragma unroll
            for (int i = 0; i < 8; i++) {
                float4 v0 = *(const float4*)(ap + i * 8);
                float4 v1 = *(const float4*)(ap + i * 8 + 4);
                uint32_t l0, l1, l2, l3;
                uint32_t h0 = split_hi2(v0.x, v0.y, l0);
                uint32_t h1 = split_hi2(v0.z, v0.w, l1);
                uint32_t h2 = split_hi2(v1.x, v1.y, l2);
                uint32_t h3 = split_hi2(v1.z, v1.w, l3);
                asm volatile("st.shared.v4.b32 [%0], {%1, %2, %3, %4};"
                             :: "r"(sAh + d + i * 16), "r"(h0), "r"(h1), "r"(h2), "r"(h3));
                asm volatile("st.shared.v4.b32 [%0], {%1, %2, %3, %4};"
                             :: "r"(sAl + d + i * 16), "r"(l0), "r"(l1), "r"(l2), "r"(l3));
            }
        }
        if (first) { cp_wait0(); first = false; }
        __syncthreads();

        float acc[4][4][4];
#pragma unroll
        for (int ni = 0; ni < 4; ni++) {
            float2 b = __ldg((const float2*)(b1 + cw * 32 + ni * 8 + tq * 2));
#pragma unroll
            for (int mi = 0; mi < 4; mi++) {
                acc[mi][ni][0] = b.x; acc[mi][ni][1] = b.y;
                acc[mi][ni][2] = b.x; acc[mi][ni][3] = b.y;
            }
        }
#pragma unroll
        for (int ks = 0; ks < 8; ks++) {
            uint32_t ah[4][4], al[4][4], bh[4][2], bl[4][2];
#pragma unroll
            for (int mi = 0; mi < 4; mi++) {
                ldx4(ah[mi], sAh + aoff + mi * 4352 + ks * 32);
                ldx4(al[mi], sAl + aoff + mi * 4352 + ks * 32);
            }
#pragma unroll
            for (int np = 0; np < 2; np++) {
                uint32_t r[4];
                ldx4(r, sW1h + b1off + np * 4352 + ks * 32);
                bh[np * 2][0] = r[0]; bh[np * 2][1] = r[1];
                bh[np * 2 + 1][0] = r[2]; bh[np * 2 + 1][1] = r[3];
                ldx4(r, sW1l + b1off + np * 4352 + ks * 32);
                bl[np * 2][0] = r[0]; bl[np * 2][1] = r[1];
                bl[np * 2 + 1][0] = r[2]; bl[np * 2 + 1][1] = r[3];
            }
#pragma unroll
            for (int mi = 0; mi < 4; mi++)
#pragma unroll
                for (int ni = 0; ni < 4; ni++) {
                    mma_bf16(acc[mi][ni], ah[mi], bh[ni]);
                    mma_bf16(acc[mi][ni], ah[mi], bl[ni]);
                    mma_bf16(acc[mi][ni], al[mi], bh[ni]);
                }
        }
        __syncthreads();

#pragma unroll
        for (int mi = 0; mi < 4; mi++) {
            const int r0 = mw * 64 + mi * 16 + g;
#pragma unroll
            for (int ni = 0; ni < 4; ni++) {
                const int col = cw * 32 + ni * 8 + tq * 2;
                float v0 = acc[mi][ni][0], v1 = acc[mi][ni][1];
                float v2 = acc[mi][ni][2], v3 = acc[mi][ni][3];
                if (ACT1 == 1) {
                    v0 = fmaxf(v0, 0.f); v1 = fmaxf(v1, 0.f);
                    v2 = fmaxf(v2, 0.f); v3 = fmaxf(v3, 0.f);
                } else {
                    v0 = tanhf(v0); v1 = tanhf(v1);
                    v2 = tanhf(v2); v3 = tanhf(v3);
                }
                uint32_t lo0, lo1;
                uint32_t hi0 = split_hi2(v0, v1, lo0);
                uint32_t hi1 = split_hi2(v2, v3, lo1);
                const uint32_t d0 = (uint32_t)r0 * 272 + col * 2;
                asm volatile("st.shared.b32 [%0], %1;" :: "r"(sAh + d0), "r"(hi0));
                asm volatile("st.shared.b32 [%0], %1;" :: "r"(sAl + d0), "r"(lo0));
                asm volatile("st.shared.b32 [%0], %1;" :: "r"(sAh + d0 + 8 * 272), "r"(hi1));
                asm volatile("st.shared.b32 [%0], %1;" :: "r"(sAl + d0 + 8 * 272), "r"(lo1));
            }
        }
        __syncthreads();

        float acc2[4][NF2][4];
#pragma unroll
        for (int ni = 0; ni < NF2; ni++) {
            float2 b = __ldg((const float2*)(b2 + cw * NW2 + ni * 8 + tq * 2));
#pragma unroll
            for (int mi = 0; mi < 4; mi++) {
                acc2[mi][ni][0] = b.x; acc2[mi][ni][1] = b.y;
                acc2[mi][ni][2] = b.x; acc2[mi][ni][3] = b.y;
            }
        }
#pragma unroll
        for (int ks = 0; ks < 8; ks++) {
            uint32_t ah[4][4], al[4][4], bh[NF2][2], bl[NF2][2];
#pragma unroll
            for (int mi = 0; mi < 4; mi++) {
                ldx4(ah[mi], sAh + aoff + mi * 4352 + ks * 32);
                ldx4(al[mi], sAl + aoff + mi * 4352 + ks * 32);
            }
#pragma unroll
            for (int np = 0; np < NF2 / 2; np++) {
                uint32_t r[4];
                ldx4(r, sW2h + b2off + np * 4352 + ks * 32);
                bh[np * 2][0] = r[0]; bh[np * 2][1] = r[1];
                bh[np * 2 + 1][0] = r[2]; bh[np * 2 + 1][1] = r[3];
                ldx4(r, sW2l + b2off + np * 4352 + ks * 32);
                bl[np * 2][0] = r[0]; bl[np * 2][1] = r[1];
                bl[np * 2 + 1][0] = r[2]; bl[np * 2 + 1][1] = r[3];
            }
#pragma unroll
            for (int mi = 0; mi < 4; mi++)
#pragma unroll
                for (int ni = 0; ni < NF2; ni++) {
                    mma_bf16(acc2[mi][ni], ah[mi], bh[ni]);
                    mma_bf16(acc2[mi][ni], ah[mi], bl[ni]);
                    mma_bf16(acc2[mi][ni], al[mi], bh[ni]);
                }
        }
        __syncthreads();

#pragma unroll
        for (int mi = 0; mi < 4; mi++) {
            const int r0 = mbase + mw * 64 + mi * 16 + g;
#pragma unroll
            for (int ni = 0; ni < NF2; ni++) {
                const int col = cw * NW2 + ni * 8 + tq * 2;
                float v0 = acc2[mi][ni][0], v1 = acc2[mi][ni][1];
                float v2 = acc2[mi][ni][2], v3 = acc2[mi][ni][3];
                if (ACT2 == 2) {
                    v0 = tanhf(v0); v1 = tanhf(v1);
                    v2 = tanhf(v2); v3 = tanhf(v3);
                }
                if (r0 < nrows) {
                    *(float2*)(out + (size_t)r0 * COUT2 + col) = make_float2(v0, v1);
                    if (out2)
                        *(float2*)(out2 + (size_t)r0 * COUT2 + col) = make_float2(v0, v1);
                }
                if (r0 + 8 < nrows) {
                    *(float2*)(out + (size_t)(r0 + 8) * COUT2 + col) = make_float2(v2, v3);
                    if (out2)
                        *(float2*)(out2 + (size_t)(r0 + 8) * COUT2 + col) = make_float2(v2, v3);
                }
            }
        }
    }
}

// ---------------- launch ------------------------------------------------------
extern "C" void kernel_launch(void* const* d_in, const int* in_sizes, int n_in,
                              void* d_out, int out_size) {
    const float* x    = (const float*)d_in[0];
    const int*   ei   = (const int*)d_in[1];
    const float* ef   = (const float*)d_in[2];
    const float* We1  = (const float*)d_in[3];
    const float* be1  = (const float*)d_in[4];
    const float* W1a  = (const float*)d_in[5];
    const float* b1a  = (const float*)d_in[6];
    const float* W1b  = (const float*)d_in[7];
    const float* b1b  = (const float*)d_in[8];
    const float* We2  = (const float*)d_in[9];
    const float* be2  = (const float*)d_in[10];
    const float* W2a  = (const float*)d_in[11];
    const float* b2a  = (const float*)d_in[12];
    const float* W2b  = (const float*)d_in[13];
    const float* b2b  = (const float*)d_in[14];
    const float* Wfc1 = (const float*)d_in[15];
    const float* bfc1 = (const float*)d_in[16];
    const float* Wfc2 = (const float*)d_in[17];
    const float* bfc2 = (const float*)d_in[18];
    float* out = (float*)d_out;

    float *agg, *h;
    __nv_bfloat16 *wb, *web;
    int *cnt, *scan, *bsum, *cur, *perm, *src2, *dst2;
    cudaGetSymbolAddress((void**)&agg,  g_agg);
    cudaGetSymbolAddress((void**)&h,    g_h);
    cudaGetSymbolAddress((void**)&wb,   g_wb);
    cudaGetSymbolAddress((void**)&web,  g_web);
    cudaGetSymbolAddress((void**)&cnt,  g_cnt);
    cudaGetSymbolAddress((void**)&scan, g_scan);
    cudaGetSymbolAddress((void**)&bsum, g_bsum);
    cudaGetSymbolAddress((void**)&cur,  g_cur);
    cudaGetSymbolAddress((void**)&perm, g_perm);
    cudaGetSymbolAddress((void**)&src2, g_src2);
    cudaGetSymbolAddress((void**)&dst2, g_dst2);
    auto WB = [&](int m, int s) { return wb + ((size_t)m * 2 + s) * 128 * 136; };
    auto WE = [&](int m, int s) { return web + ((size_t)m * 2 + s) * 128 * 40; };

    const int* srcp = ei;
    const int* dstp = ei + Ee;

    const int n4 = Nn * 128 / 4;
    const int cpG = (n4 + 255) / 256;
    const int egG = (Ee + 127) / 128;            // 4688
    const int eG256 = (Ee + 255) / 256;          // 2344
    const int nG256 = (Nn + 255) / 256;          // 391
    const int ntiles = (Nn + 127) / 128;         // 782

    constexpr int SME   = 68608;
    constexpr int SMF128 = 6 * 128 * 136 * 2;
    constexpr int SMF64  = 4 * 128 * 136 * 2 + 2 * 64 * 136 * 2;
    cudaFuncSetAttribute(edge_kernel, cudaFuncAttributeMaxDynamicSharedMemorySize, SME);
    cudaFuncSetAttribute(fgemm<128, 1, 2>, cudaFuncAttributeMaxDynamicSharedMemorySize, SMF128);
    cudaFuncSetAttribute(fgemm<64, 2, 0>,  cudaFuncAttributeMaxDynamicSharedMemorySize, SMF64);

    // weight prep + edge sort (by dst)
    prep_all<<<384, 256>>>(W1a, W1b, W2a, W2b, Wfc1, Wfc2, We1, We2, wb, web);
    k_zero<<<nG256, 256>>>(cnt);
    k_hist<<<eG256, 256>>>(dstp, cnt);
    k_scan1<<<nG256, 256>>>(cnt, scan, bsum);
    k_scan2<<<1, 512>>>(bsum, nG256);
    k_scan3<<<nG256, 256>>>(scan, bsum, cur);
    k_scatter<<<eG256, 256>>>(srcp, dstp, cur, perm, src2, dst2);

    // Layer 1
    copy_kernel<<<cpG, 256>>>((float4*)agg, (const float4*)x, n4);
    edge_kernel<<<egG, 256, SME>>>(x, src2, dst2, perm, ef, WE(0, 0), WE(0, 1), be1, agg);
    fgemm<128, 1, 2><<<148, 256, SMF128>>>(agg, WB(0, 0), WB(0, 1), WB(1, 0), WB(1, 1),
                                           b1a, b1b, h, agg, Nn, ntiles);

    // Layer 2
    edge_kernel<<<egG, 256, SME>>>(h, src2, dst2, perm, ef, WE(1, 0), WE(1, 1), be2, agg);
    fgemm<128, 1, 2><<<148, 256, SMF128>>>(agg, WB(2, 0), WB(2, 1), WB(3, 0), WB(3, 1),
                                           b2a, b2b, h, nullptr, Nn, ntiles);

    // Head
    fgemm<64, 2, 0><<<148, 256, SMF64>>>(h, WB(4, 0), WB(4, 1), WB(5, 0), WB(5, 1),
                                         bfc1, bfc2, out, nullptr, Nn, ntiles);
}

// round 8
// speedup vs baseline: 1.2045x; 1.2045x over previous
#include <cuda_runtime.h>
#include <cuda_bf16.h>
#include <cstdint>

#define Nn 100000
#define Ee 600000

// ---------------- scratch (allocation-free: __device__ globals) --------------
__device__ float g_agg[Nn * 128];
__device__ float g_h[Nn * 128];
__device__ __align__(16) __nv_bfloat16 g_wb[6][2][128 * 136];
__device__ __align__(16) __nv_bfloat16 g_web[2][2][128 * 40];

// ---------------- helpers -----------------------------------------------------
__device__ __forceinline__ void red_add_v2(float* p, float2 v) {
    asm volatile("red.global.add.v2.f32 [%0], {%1, %2};"
                 :: "l"(p), "f"(v.x), "f"(v.y) : "memory");
}
__device__ __forceinline__ uint32_t smem_u32(const void* p) {
    return (uint32_t)__cvta_generic_to_shared(p);
}
__device__ __forceinline__ void cp_async16(uint32_t dst, const void* src) {
    asm volatile("cp.async.cg.shared.global [%0], [%1], 16;"
                 :: "r"(dst), "l"(src));
}
__device__ __forceinline__ void cp_commit() {
    asm volatile("cp.async.commit_group;");
}
__device__ __forceinline__ void cp_wait0() {
    asm volatile("cp.async.wait_group 0;" ::: "memory");
}
__device__ __forceinline__ void ldx4(uint32_t* r, uint32_t addr) {
    asm volatile("ldmatrix.sync.aligned.m8n8.x4.shared.b16 {%0, %1, %2, %3}, [%4];"
                 : "=r"(r[0]), "=r"(r[1]), "=r"(r[2]), "=r"(r[3]) : "r"(addr));
}
__device__ __forceinline__ void mma_bf16(float* c, const uint32_t* a,
                                         const uint32_t* b) {
    asm volatile("mma.sync.aligned.m16n8k16.row.col.f32.bf16.bf16.f32 "
                 "{%0, %1, %2, %3}, {%4, %5, %6, %7}, {%8, %9}, {%0, %1, %2, %3};"
                 : "+f"(c[0]), "+f"(c[1]), "+f"(c[2]), "+f"(c[3])
                 : "r"(a[0]), "r"(a[1]), "r"(a[2]), "r"(a[3]),
                   "r"(b[0]), "r"(b[1]));
}
__device__ __forceinline__ uint32_t bf2_u32(__nv_bfloat162 x) {
    uint32_t r;
    memcpy(&r, &x, 4);
    return r;
}
__device__ __forceinline__ uint32_t split_hi2(float a, float b, uint32_t& lo) {
    __nv_bfloat162 h = __floats2bfloat162_rn(a, b);
    __nv_bfloat162 l = __floats2bfloat162_rn(a - __bfloat162float(h.x),
                                             b - __bfloat162float(h.y));
    lo = bf2_u32(l);
    return bf2_u32(h);
}
// ---- bulk copy + mbarrier (sm_90 baseline PTX, legal on compute_103) ----
__device__ __forceinline__ void mbar_init(uint32_t mb, uint32_t cnt) {
    asm volatile("mbarrier.init.shared.b64 [%0], %1;" :: "r"(mb), "r"(cnt) : "memory");
}
__device__ __forceinline__ void mbar_expect(uint32_t mb, uint32_t bytes) {
    asm volatile("mbarrier.arrive.expect_tx.shared.b64 _, [%0], %1;"
                 :: "r"(mb), "r"(bytes) : "memory");
}
__device__ __forceinline__ void bulk_ld(uint32_t dst, const void* src,
                                        uint32_t bytes, uint32_t mb) {
    asm volatile("cp.async.bulk.shared::cta.global.mbarrier::complete_tx::bytes "
                 "[%0], [%1], %2, [%3];"
                 :: "r"(dst), "l"(src), "r"(bytes), "r"(mb) : "memory");
}
__device__ __forceinline__ void mbar_wait(uint32_t mb, uint32_t parity) {
    uint32_t done;
    asm volatile("{\n\t.reg .pred p;\n\t"
                 "mbarrier.try_wait.parity.acquire.cta.shared::cta.b64 p, [%1], %2;\n\t"
                 "selp.b32 %0, 1, 0, p;\n\t}"
                 : "=r"(done) : "r"(mb), "r"(parity) : "memory");
    if (!done) {
        asm volatile("{\n\t.reg .pred P1;\n\t"
                     "WL_%=:\n\t"
                     "mbarrier.try_wait.parity.acquire.cta.shared::cta.b64 P1, [%0], %1, 0x989680;\n\t"
                     "@P1 bra.uni WD_%=;\n\t"
                     "bra.uni WL_%=;\n\t"
                     "WD_%=:\n\t}"
                     :: "r"(mb), "r"(parity) : "memory");
    }
}

// ---------------- init copy ---------------------------------------------------
__global__ void __launch_bounds__(256) copy_kernel(float4* __restrict__ dst,
                                                   const float4* __restrict__ src,
                                                   int n4) {
    int i = blockIdx.x * blockDim.x + threadIdx.x;
    if (i < n4) dst[i] = src[i];
}

// ---------------- fused weight prep (one launch) -------------------------------
__global__ void __launch_bounds__(256)
prep_all(const float* __restrict__ W1a, const float* __restrict__ W1b,
         const float* __restrict__ W2a, const float* __restrict__ W2b,
         const float* __restrict__ Wfc1, const float* __restrict__ Wfc2,
         const float* __restrict__ We1, const float* __restrict__ We2,
         __nv_bfloat16* __restrict__ wb, __nv_bfloat16* __restrict__ web) {
    int id = blockIdx.x * 256 + threadIdx.x;
    if (id < 81920) {
        int m = id / 16384, e = id % 16384;
        const float* W = (m == 0) ? W1a : (m == 1) ? W1b
                       : (m == 2) ? W2a : (m == 3) ? W2b : Wfc1;
        int n = e >> 7, k = e & 127;
        float v = W[k * 128 + n];
        __nv_bfloat16 h = __float2bfloat16_rn(v);
        __nv_bfloat16 l = __float2bfloat16_rn(v - __bfloat162float(h));
        wb[(size_t)m * 2 * 128 * 136 + n * 136 + k] = h;
        wb[((size_t)m * 2 + 1) * 128 * 136 + n * 136 + k] = l;
    } else if (id < 90112) {
        int e = id - 81920;
        int n = e >> 7, k = e & 127;
        float v = Wfc2[k * 64 + n];
        __nv_bfloat16 h = __float2bfloat16_rn(v);
        __nv_bfloat16 l = __float2bfloat16_rn(v - __bfloat162float(h));
        wb[(size_t)5 * 2 * 128 * 136 + n * 136 + k] = h;
        wb[((size_t)5 * 2 + 1) * 128 * 136 + n * 136 + k] = l;
    } else if (id < 98304) {
        int e = id - 90112;
        int m = e >> 12; e &= 4095;
        int n = e >> 5, k = e & 31;
        const float* We = m ? We2 : We1;
        float v = We[k * 128 + n];
        __nv_bfloat16 h = __float2bfloat16_rn(v);
        __nv_bfloat16 l = __float2bfloat16_rn(v - __bfloat162float(h));
        web[(size_t)m * 2 * 128 * 40 + n * 40 + k] = h;
        web[((size_t)m * 2 + 1) * 128 * 40 + n * 40 + k] = l;
    }
}

// ---------------- HMMA fused edge kernel (R6 form — best known) ---------------
__global__ void __launch_bounds__(256, 2)
edge_kernel(const float* __restrict__ xin,
            const int* __restrict__ src, const int* __restrict__ dst,
            const float* __restrict__ ef,
            const __nv_bfloat16* __restrict__ Weh,
            const __nv_bfloat16* __restrict__ Wel,
            const float* __restrict__ be,
            float* __restrict__ agg) {
    __shared__ __align__(16) __nv_bfloat16 sWeh[128 * 40], sWel[128 * 40];
    __shared__ __align__(16) __nv_bfloat16 sEfh[128 * 40], sEfl[128 * 40];
    __shared__ float sbias[128];
    __shared__ int ssrc[128], sdst[128];

    const int tid  = threadIdx.x;
    const int wid  = tid >> 5;
    const int lane = tid & 31;
    const int base = blockIdx.x * 128;
    const int nvalid = min(128, Ee - base);

    const uint32_t swh = smem_u32(sWeh), swl = smem_u32(sWel);
    for (int i = tid; i < 640; i += 256) {
        cp_async16(swh + i * 16, (const char*)Weh + i * 16);
        cp_async16(swl + i * 16, (const char*)Wel + i * 16);
    }
    cp_commit();

    if (tid < 128) {
        sbias[tid] = be[tid];
        int e = min(base + tid, Ee - 1);
        ssrc[tid] = src[e];
        sdst[tid] = dst[e];
    }

    {
        const int edge = tid >> 1, half = tid & 1;
        int ge = min(base + edge, Ee - 1);
        const float4* ap = (const float4*)(ef + (size_t)ge * 32 + half * 16);
        const uint32_t dh = smem_u32(sEfh) + edge * 80 + half * 32;
        const uint32_t dl = smem_u32(sEfl) + edge * 80 + half * 32;
#pragma unroll
        for (int i = 0; i < 4; i++) {
            float4 v = ap[i];
            uint32_t l0, l1;
            uint32_t h0 = split_hi2(v.x, v.y, l0);
            uint32_t h1 = split_hi2(v.z, v.w, l1);
            asm volatile("st.shared.v2.b32 [%0], {%1, %2};"
                         :: "r"(dh + i * 8), "r"(h0), "r"(h1));
            asm volatile("st.shared.v2.b32 [%0], {%1, %2};"
                         :: "r"(dl + i * 8), "r"(l0), "r"(l1));
        }
    }
    cp_wait0();
    __syncthreads();

    const int g = lane >> 2, tq = lane & 3;
    const uint32_t aoff = smem_u32(sEfh)
        + (uint32_t)(wid * 16 + (lane & 15)) * 80 + ((lane >> 4) ? 16 : 0);
    const uint32_t aloff = aoff + (smem_u32(sEfl) - smem_u32(sEfh));
    const int brow = (lane & 7) + ((lane >> 4) << 3);
    const uint32_t boff = smem_u32(sWeh) + (uint32_t)brow * 80 + ((lane & 8) ? 16 : 0);
    const uint32_t bloff = boff + (smem_u32(sWel) - smem_u32(sWeh));

    float acc[16][4];
#pragma unroll
    for (int ni = 0; ni < 16; ni++) {
        float2 b = *(const float2*)(sbias + ni * 8 + tq * 2);
        acc[ni][0] = b.x; acc[ni][1] = b.y;
        acc[ni][2] = b.x; acc[ni][3] = b.y;
    }

#pragma unroll
    for (int ks = 0; ks < 2; ks++) {
        uint32_t ah[4], al[4];
        ldx4(ah, aoff + ks * 32);
        ldx4(al, aloff + ks * 32);
#pragma unroll
        for (int np = 0; np < 8; np++) {
            uint32_t rh[4], rl[4];
            ldx4(rh, boff + np * (16 * 80) + ks * 32);
            ldx4(rl, bloff + np * (16 * 80) + ks * 32);
            uint32_t bh0[2] = {rh[0], rh[1]}, bh1[2] = {rh[2], rh[3]};
            uint32_t bl0[2] = {rl[0], rl[1]}, bl1[2] = {rl[2], rl[3]};
            mma_bf16(acc[np * 2],     ah, bh0);
            mma_bf16(acc[np * 2],     ah, bl0);
            mma_bf16(acc[np * 2],     al, bh0);
            mma_bf16(acc[np * 2 + 1], ah, bh1);
            mma_bf16(acc[np * 2 + 1], ah, bl1);
            mma_bf16(acc[np * 2 + 1], al, bh1);
        }
    }

    const int er0 = wid * 16 + g;
#pragma unroll
    for (int half = 0; half < 2; half++) {
        const int er = er0 + half * 8;
        if (er < nvalid) {
            const size_t srow = (size_t)ssrc[er] * 128;
            const size_t drow = (size_t)sdst[er] * 128;
#pragma unroll
            for (int ni = 0; ni < 16; ni++) {
                const int col = ni * 8 + tq * 2;
                float2 xv = *(const float2*)(xin + srow + col);
                float2 m;
                m.x = fmaxf(xv.x + acc[ni][half * 2 + 0], 0.f);
                m.y = fmaxf(xv.y + acc[ni][half * 2 + 1], 0.f);
                red_add_v2(agg + drow + col, m);
            }
        }
    }
}

// ---------------- fused two-stage node GEMM v2 --------------------------------
// 128 thr (4 warps), M-tile 64, 2 CTAs/SM. Single W buffer alternates W1/W2,
// streamed per tile via cp.async.bulk + mbarrier. T tile overwrites A buffer.
// W1/W2 point at contiguous hi||lo blocks (34816 B each half).
template <int COUT2, int ACT1, int ACT2>
__global__ void __launch_bounds__(128, 2)
fgemm(const float* __restrict__ A,
      const __nv_bfloat16* __restrict__ W1, const __nv_bfloat16* __restrict__ W2,
      const float* __restrict__ b1, const float* __restrict__ b2,
      float* __restrict__ out, float* __restrict__ out2, int nrows, int ntiles) {
    constexpr int NW2 = COUT2 / 4;
    constexpr int NF2 = NW2 / 8;
    constexpr uint32_t AB  = 64 * 272;      // 17408 per A half
    constexpr uint32_t WHB = 128 * 272;     // 34816 per W half
    constexpr uint32_t WBYTES = 2 * WHB;    // 69632 (hi||lo, one bulk)

    extern __shared__ char sm[];
    const uint32_t s0  = smem_u32(sm);
    const uint32_t sAh = s0, sAl = s0 + AB;
    const uint32_t sWh = s0 + 2 * AB, sWl = sWh + WHB;
    __shared__ __align__(8) unsigned long long bw_store;
    const uint32_t bw = smem_u32(&bw_store);

    const int tid  = threadIdx.x;
    const int wid  = tid >> 5;               // = cw (col-warp)
    const int lane = tid & 31;
    const int cw   = wid;

    if (tid == 0) mbar_init(bw, 1);
    __syncthreads();
    if (tid == 0) { mbar_expect(bw, WBYTES); bulk_ld(sWh, W1, WBYTES, bw); }

    const int g = lane >> 2, tq = lane & 3;
    const uint32_t aoff = (uint32_t)(lane & 15) * 272 + ((lane >> 4) ? 16 : 0);
    const int brow = (lane & 7) + ((lane >> 4) << 3);
    const uint32_t b1off = (uint32_t)(cw * 32 + brow) * 272 + ((lane & 8) ? 16 : 0);
    const uint32_t b2off = (uint32_t)(cw * NW2 + brow) * 272 + ((lane & 8) ? 16 : 0);

    int ph = 0;
    for (int mt = blockIdx.x; mt < ntiles; mt += gridDim.x) {
        const int mbase = mt * 64;

        // ---- A tile: 64 x 128 fp32 -> bf16 hi/lo (overlaps W bulk in flight) --
        {
            const int row = tid >> 1, half = tid & 1;
            int grow = min(mbase + row, nrows - 1);
            const float* ap = A + (size_t)grow * 128 + half * 64;
            const uint32_t d = row * 272 + half * 128;
#pragma unroll
            for (int i = 0; i < 8; i++) {
                float4 v0 = *(const float4*)(ap + i * 8);
                float4 v1 = *(const float4*)(ap + i * 8 + 4);
                uint32_t l0, l1, l2, l3;
                uint32_t h0 = split_hi2(v0.x, v0.y, l0);
                uint32_t h1 = split_hi2(v0.z, v0.w, l1);
                uint32_t h2 = split_hi2(v1.x, v1.y, l2);
                uint32_t h3 = split_hi2(v1.z, v1.w, l3);
                asm volatile("st.shared.v4.b32 [%0], {%1, %2, %3, %4};"
                             :: "r"(sAh + d + i * 16), "r"(h0), "r"(h1), "r"(h2), "r"(h3));
                asm volatile("st.shared.v4.b32 [%0], {%1, %2, %3, %4};"
                             :: "r"(sAl + d + i * 16), "r"(l0), "r"(l1), "r"(l2), "r"(l3));
            }
        }
        __syncthreads();
        mbar_wait(bw, ph & 1); ph++;          // W1 resident

        // ---- stage 1: T = act1(A @ W1 + b1), warp cols [32*cw, +32) ----------
        float acc[4][4][4];
#pragma unroll
        for (int ni = 0; ni < 4; ni++) {
            float2 b = __ldg((const float2*)(b1 + cw * 32 + ni * 8 + tq * 2));
#pragma unroll
            for (int mi = 0; mi < 4; mi++) {
                acc[mi][ni][0] = b.x; acc[mi][ni][1] = b.y;
                acc[mi][ni][2] = b.x; acc[mi][ni][3] = b.y;
            }
        }
#pragma unroll
        for (int ks = 0; ks < 8; ks++) {
            uint32_t ah[4][4], al[4][4], bh[4][2], bl[4][2];
#pragma unroll
            for (int mi = 0; mi < 4; mi++) {
                ldx4(ah[mi], sAh + aoff + mi * 4352 + ks * 32);
                ldx4(al[mi], sAl + aoff + mi * 4352 + ks * 32);
            }
#pragma unroll
            for (int np = 0; np < 2; np++) {
                uint32_t r[4];
                ldx4(r, sWh + b1off + np * 4352 + ks * 32);
                bh[np * 2][0] = r[0]; bh[np * 2][1] = r[1];
                bh[np * 2 + 1][0] = r[2]; bh[np * 2 + 1][1] = r[3];
                ldx4(r, sWl + b1off + np * 4352 + ks * 32);
                bl[np * 2][0] = r[0]; bl[np * 2][1] = r[1];
                bl[np * 2 + 1][0] = r[2]; bl[np * 2 + 1][1] = r[3];
            }
#pragma unroll
            for (int mi = 0; mi < 4; mi++)
#pragma unroll
                for (int ni = 0; ni < 4; ni++) {
                    mma_bf16(acc[mi][ni], ah[mi], bh[ni]);
                    mma_bf16(acc[mi][ni], ah[mi], bl[ni]);
                    mma_bf16(acc[mi][ni], al[mi], bh[ni]);
                }
        }
        __syncthreads();                      // W buffer + A reads done

        // stream W2 while we write T
        if (tid == 0) { mbar_expect(bw, WBYTES); bulk_ld(sWh, W2, WBYTES, bw); }

        // ---- write T (act1 + bf16 split) over the A buffer --------------------
#pragma unroll
        for (int mi = 0; mi < 4; mi++) {
            const int r0 = mi * 16 + g;
#pragma unroll
            for (int ni = 0; ni < 4; ni++) {
                const int col = cw * 32 + ni * 8 + tq * 2;
                float v0 = acc[mi][ni][0], v1 = acc[mi][ni][1];
                float v2 = acc[mi][ni][2], v3 = acc[mi][ni][3];
                if (ACT1 == 1) {
                    v0 = fmaxf(v0, 0.f); v1 = fmaxf(v1, 0.f);
                    v2 = fmaxf(v2, 0.f); v3 = fmaxf(v3, 0.f);
                } else {
                    v0 = tanhf(v0); v1 = tanhf(v1);
                    v2 = tanhf(v2); v3 = tanhf(v3);
                }
                uint32_t lo0, lo1;
                uint32_t hi0 = split_hi2(v0, v1, lo0);
                uint32_t hi1 = split_hi2(v2, v3, lo1);
                const uint32_t d0 = (uint32_t)r0 * 272 + col * 2;
                asm volatile("st.shared.b32 [%0], %1;" :: "r"(sAh + d0), "r"(hi0));
                asm volatile("st.shared.b32 [%0], %1;" :: "r"(sAl + d0), "r"(lo0));
                asm volatile("st.shared.b32 [%0], %1;" :: "r"(sAh + d0 + 8 * 272), "r"(hi1));
                asm volatile("st.shared.b32 [%0], %1;" :: "r"(sAl + d0 + 8 * 272), "r"(lo1));
            }
        }
        __syncthreads();                      // T visible
        mbar_wait(bw, ph & 1); ph++;          // W2 resident

        // ---- stage 2: out = act2(T @ W2 + b2), warp cols [NW2*cw, +NW2) -------
        float acc2[4][NF2][4];
#pragma unroll
        for (int ni = 0; ni < NF2; ni++) {
            float2 b = __ldg((const float2*)(b2 + cw * NW2 + ni * 8 + tq * 2));
#pragma unroll
            for (int mi = 0; mi < 4; mi++) {
                acc2[mi][ni][0] = b.x; acc2[mi][ni][1] = b.y;
                acc2[mi][ni][2] = b.x; acc2[mi][ni][3] = b.y;
            }
        }
#pragma unroll
        for (int ks = 0; ks < 8; ks++) {
            uint32_t ah[4][4], al[4][4], bh[NF2][2], bl[NF2][2];
#pragma unroll
            for (int mi = 0; mi < 4; mi++) {
                ldx4(ah[mi], sAh + aoff + mi * 4352 + ks * 32);
                ldx4(al[mi], sAl + aoff + mi * 4352 + ks * 32);
            }
#pragma unroll
            for (int np = 0; np < NF2 / 2; np++) {
                uint32_t r[4];
                ldx4(r, sWh + b2off + np * 4352 + ks * 32);
                bh[np * 2][0] = r[0]; bh[np * 2][1] = r[1];
                bh[np * 2 + 1][0] = r[2]; bh[np * 2 + 1][1] = r[3];
                ldx4(r, sWl + b2off + np * 4352 + ks * 32);
                bl[np * 2][0] = r[0]; bl[np * 2][1] = r[1];
                bl[np * 2 + 1][0] = r[2]; bl[np * 2 + 1][1] = r[3];
            }
#pragma unroll
            for (int mi = 0; mi < 4; mi++)
#pragma unroll
                for (int ni = 0; ni < NF2; ni++) {
                    mma_bf16(acc2[mi][ni], ah[mi], bh[ni]);
                    mma_bf16(acc2[mi][ni], ah[mi], bl[ni]);
                    mma_bf16(acc2[mi][ni], al[mi], bh[ni]);
                }
        }
        __syncthreads();                      // T + W reads done

        // stream next tile's W1 while the epilogue stores
        if (tid == 0 && mt + gridDim.x < ntiles) {
            mbar_expect(bw, WBYTES); bulk_ld(sWh, W1, WBYTES, bw);
        }

        // ---- epilogue ---------------------------------------------------------
#pragma unroll
        for (int mi = 0; mi < 4; mi++) {
            const int r0 = mbase + mi * 16 + g;
#pragma unroll
            for (int ni = 0; ni < NF2; ni++) {
                const int col = cw * NW2 + ni * 8 + tq * 2;
                float v0 = acc2[mi][ni][0], v1 = acc2[mi][ni][1];
                float v2 = acc2[mi][ni][2], v3 = acc2[mi][ni][3];
                if (ACT2 == 2) {
                    v0 = tanhf(v0); v1 = tanhf(v1);
                    v2 = tanhf(v2); v3 = tanhf(v3);
                }
                if (r0 < nrows) {
                    *(float2*)(out + (size_t)r0 * COUT2 + col) = make_float2(v0, v1);
                    if (out2)
                        *(float2*)(out2 + (size_t)r0 * COUT2 + col) = make_float2(v0, v1);
                }
                if (r0 + 8 < nrows) {
                    *(float2*)(out + (size_t)(r0 + 8) * COUT2 + col) = make_float2(v2, v3);
                    if (out2)
                        *(float2*)(out2 + (size_t)(r0 + 8) * COUT2 + col) = make_float2(v2, v3);
                }
            }
        }
    }
}

// ---------------- launch ------------------------------------------------------
extern "C" void kernel_launch(void* const* d_in, const int* in_sizes, int n_in,
                              void* d_out, int out_size) {
    const float* x    = (const float*)d_in[0];
    const int*   ei   = (const int*)d_in[1];
    const float* ef   = (const float*)d_in[2];
    const float* We1  = (const float*)d_in[3];
    const float* be1  = (const float*)d_in[4];
    const float* W1a  = (const float*)d_in[5];
    const float* b1a  = (const float*)d_in[6];
    const float* W1b  = (const float*)d_in[7];
    const float* b1b  = (const float*)d_in[8];
    const float* We2  = (const float*)d_in[9];
    const float* be2  = (const float*)d_in[10];
    const float* W2a  = (const float*)d_in[11];
    const float* b2a  = (const float*)d_in[12];
    const float* W2b  = (const float*)d_in[13];
    const float* b2b  = (const float*)d_in[14];
    const float* Wfc1 = (const float*)d_in[15];
    const float* bfc1 = (const float*)d_in[16];
    const float* Wfc2 = (const float*)d_in[17];
    const float* bfc2 = (const float*)d_in[18];
    float* out = (float*)d_out;

    float *agg, *h;
    __nv_bfloat16 *wb, *web;
    cudaGetSymbolAddress((void**)&agg, g_agg);
    cudaGetSymbolAddress((void**)&h,   g_h);
    cudaGetSymbolAddress((void**)&wb,  g_wb);
    cudaGetSymbolAddress((void**)&web, g_web);
    auto WB = [&](int m) { return wb + (size_t)m * 2 * 128 * 136; };   // hi||lo base
    auto WE = [&](int m, int s) { return web + ((size_t)m * 2 + s) * 128 * 40; };

    const int* srcp = ei;
    const int* dstp = ei + Ee;

    const int n4 = Nn * 128 / 4;
    const int cpG = (n4 + 255) / 256;
    const int egG = (Ee + 127) / 128;            // 4688
    const int ntiles = (Nn + 63) / 64;           // 1563
    const int gG = 296;                          // 2 persistent CTAs/SM

    constexpr int SMF = 2 * 17408 + 2 * 34816;   // 104448
    cudaFuncSetAttribute(fgemm<128, 1, 2>, cudaFuncAttributeMaxDynamicSharedMemorySize, SMF);
    cudaFuncSetAttribute(fgemm<64, 2, 0>,  cudaFuncAttributeMaxDynamicSharedMemorySize, SMF);

    prep_all<<<384, 256>>>(W1a, W1b, W2a, W2b, Wfc1, Wfc2, We1, We2, wb, web);

    // Layer 1
    copy_kernel<<<cpG, 256>>>((float4*)agg, (const float4*)x, n4);
    edge_kernel<<<egG, 256>>>(x, srcp, dstp, ef, WE(0, 0), WE(0, 1), be1, agg);
    fgemm<128, 1, 2><<<gG, 128, SMF>>>(agg, WB(0), WB(1), b1a, b1b, h, agg, Nn, ntiles);

    // Layer 2
    edge_kernel<<<egG, 256>>>(h, srcp, dstp, ef, WE(1, 0), WE(1, 1), be2, agg);
    fgemm<128, 1, 2><<<gG, 128, SMF>>>(agg, WB(2), WB(3), b2a, b2b, h, nullptr, Nn, ntiles);

    // Head
    fgemm<64, 2, 0><<<gG, 128, SMF>>>(h, WB(4), WB(5), bfc1, bfc2, out, nullptr, Nn, ntiles);
}